// round 4
// baseline (speedup 1.0000x reference)
#include <cuda_runtime.h>
#include <cstdint>

// Problem constants
#define BB 32
#define CC 256
#define DD 768

// Tiling
#define DTILE 128                 // M rows (d) per d-tile
#define KSTEP 32                  // e columns per pipeline stage
#define NDTILES (DD / DTILE)      // 6
#define KSTAGES (DD / KSTEP)      // 24
#define NSTAGES_TOTAL (NDTILES * KSTAGES)  // 144
#define SBUF 3                    // pipeline depth (buffers)

// Padded shared strides (floats) — chosen for conflict-free fragment LDS
#define LDIFF 772                 // 772 % 32 == 4  -> bank = (4*b + e) % 32, bijective
#define LSTG 36                   //  36 % 32 == 4  -> bank = (4*d + e) % 32, bijective

#define DIFF_SZ (BB * LDIFF)          // 24704 floats
#define STG_SZ  (DTILE * LSTG)        // 4608 floats
#define SMEM_FLOATS (DIFF_SZ + SBUF * STG_SZ + 256)   // + warp-reduce scratch

__device__ __forceinline__ uint32_t f2tf(float f) {
    uint32_t r;
    asm("cvt.rna.tf32.f32 %0, %1;\n" : "=r"(r) : "f"(f));
    return r;
}

__device__ __forceinline__ void mma_tf32(float* c,
                                         uint32_t a0, uint32_t a1, uint32_t a2, uint32_t a3,
                                         uint32_t b0, uint32_t b1) {
    asm volatile(
        "mma.sync.aligned.m16n8k8.row.col.f32.tf32.tf32.f32 "
        "{%0,%1,%2,%3}, {%4,%5,%6,%7}, {%8,%9}, {%0,%1,%2,%3};\n"
        : "+f"(c[0]), "+f"(c[1]), "+f"(c[2]), "+f"(c[3])
        : "r"(a0), "r"(a1), "r"(a2), "r"(a3), "r"(b0), "r"(b1));
}

__device__ __forceinline__ void cp_async16(float* sdst, const float* gsrc) {
    unsigned saddr = (unsigned)__cvta_generic_to_shared(sdst);
    asm volatile("cp.async.cg.shared.global [%0], [%1], 16;\n"
                 :: "r"(saddr), "l"(gsrc));
}

__device__ __forceinline__ void cp_commit() {
    asm volatile("cp.async.commit_group;\n" ::: "memory");
}

// Issue all loads for pipeline stage s: M rows [dt*128, dt*128+128), cols [ks*32, ks*32+32)
// 128 rows x 128 bytes; each thread does 4x 16B cp.async (one full 128B line per row).
__device__ __forceinline__ void issue_stage(const float* __restrict__ Mbase,
                                            float* __restrict__ sstg,
                                            int s, int tid) {
    const int dt = s / KSTAGES;
    const int ks = s - dt * KSTAGES;
    const float* base = Mbase + (size_t)(dt * DTILE) * DD + ks * KSTEP;
    float* dst = sstg + (s % SBUF) * STG_SZ;
#pragma unroll
    for (int j = 0; j < 4; j++) {
        int idx  = tid + j * 256;     // 0..1023
        int row  = idx >> 3;          // 0..127
        int col4 = (idx & 7) << 2;    // 0,4,...,28
        cp_async16(dst + row * LSTG + col4, base + (size_t)row * DD + col4);
    }
    cp_commit();
}

__global__ void __launch_bounds__(256, 1)
fecam_score_kernel(const float* __restrict__ x,      // [32,768]
                   const float* __restrict__ mu,     // [256,768]
                   const float* __restrict__ g,      // [256,768]
                   const float* __restrict__ Minv,   // [256,768,768]
                   float* __restrict__ out)          // [32,256]
{
    extern __shared__ float smem[];
    float* sdiff = smem;                       // [32][772] fp32 diff
    float* sstg  = smem + DIFF_SZ;             // 3 x [128][36] M stages
    float* sred  = smem + DIFF_SZ + SBUF * STG_SZ;  // [8][32]

    const int c    = blockIdx.x;
    const int tid  = threadIdx.x;
    const int w    = tid >> 5;
    const int lane = tid & 31;
    const int grp  = lane >> 2;   // 0..7
    const int q    = lane & 3;    // 0..3

    // ---- Phase 1: diff[b][e] = (x[b][e] - mu[c][e]) / g[c][e], fp32 in smem ----
    // Stage buffers are free right now; use them as scratch for recip / mu*recip.
    {
        float* srecip = sstg;
        float* smun   = sstg + DD;
        for (int e = tid; e < DD; e += 256) {
            float r = 1.0f / g[(size_t)c * DD + e];
            srecip[e] = r;
            smun[e]   = mu[(size_t)c * DD + e] * r;
        }
        __syncthreads();
        for (int b = 0; b < BB; b++) {
            for (int e = tid; e < DD; e += 256) {
                sdiff[b * LDIFF + e] = x[b * DD + e] * srecip[e] - smun[e];
            }
        }
        __syncthreads();
    }

    const float* Mbase = Minv + (size_t)c * DD * DD;

    // Accumulators: warp owns d rows [dt*128 + w*16, +16), all 32 batch cols.
    // acc[t][0..3] = mma C frag for n-tile t (b = t*8..t*8+7).
    float acc[4][4];
#pragma unroll
    for (int t = 0; t < 4; t++)
#pragma unroll
        for (int i = 0; i < 4; i++) acc[t][i] = 0.0f;

    // Per-thread dist partials: part[2t+j] for b = t*8 + 2q + j
    float part[8];
#pragma unroll
    for (int i = 0; i < 8; i++) part[i] = 0.0f;

    // ---- Phase 2: pipelined stream of M_c ----
    issue_stage(Mbase, sstg, 0, tid);
    issue_stage(Mbase, sstg, 1, tid);

    for (int s = 0; s < NSTAGES_TOTAL; s++) {
        asm volatile("cp.async.wait_group 1;\n" ::: "memory");
        __syncthreads();

        // Keep exactly one group committed per iteration (empty at the tail),
        // so wait_group 1 always means "stage s is resident".
        if (s + 2 < NSTAGES_TOTAL) issue_stage(Mbase, sstg, s + 2, tid);
        else                       cp_commit();

        const int dt = s / KSTAGES;
        const int ks = s - dt * KSTAGES;
        const float* stg = sstg + (s % SBUF) * STG_SZ;
        const int rowA = (w << 4) + grp;          // d row within d-tile

#pragma unroll
        for (int kk = 0; kk < 4; kk++) {          // 4 x k8 per stage
            const int eK = kk * 8;
            // A = M tile, row-major [d][e] (natural layout)
            const float* ap = stg + rowA * LSTG + eK + q;
            uint32_t a0 = f2tf(ap[0]);
            uint32_t a1 = f2tf(ap[8 * LSTG]);
            uint32_t a2 = f2tf(ap[4]);
            uint32_t a3 = f2tf(ap[8 * LSTG + 4]);

            const int eB = ks * KSTEP + eK + q;   // absolute e (k index)
#pragma unroll
            for (int t = 0; t < 4; t++) {         // 4 n-tiles cover b=0..31
                const float* bp = sdiff + (t * 8 + grp) * LDIFF + eB;
                uint32_t b0 = f2tf(bp[0]);
                uint32_t b1 = f2tf(bp[4]);
                mma_tf32(acc[t], a0, a1, a2, a3, b0, b1);
            }
        }

        // End of a d-tile: fold u[b,d] into dist partials with fp32 diff, reset acc.
        if (ks == KSTAGES - 1) {
            const int dA = dt * DTILE + (w << 4) + grp;   // absolute d of c0/c1 rows
#pragma unroll
            for (int t = 0; t < 4; t++) {
                const int b0i = t * 8 + (q << 1);
                part[2 * t] += sdiff[b0i * LDIFF + dA] * acc[t][0]
                             + sdiff[b0i * LDIFF + dA + 8] * acc[t][2];
                part[2 * t + 1] += sdiff[(b0i + 1) * LDIFF + dA] * acc[t][1]
                                 + sdiff[(b0i + 1) * LDIFF + dA + 8] * acc[t][3];
                acc[t][0] = acc[t][1] = acc[t][2] = acc[t][3] = 0.0f;
            }
        }
    }

    // ---- Reduction: lanes sharing q hold the same b set; reduce over grp bits ----
#pragma unroll
    for (int i = 0; i < 8; i++) {
        part[i] += __shfl_xor_sync(0xffffffffu, part[i], 4);
        part[i] += __shfl_xor_sync(0xffffffffu, part[i], 8);
        part[i] += __shfl_xor_sync(0xffffffffu, part[i], 16);
    }
    if (lane < 4) {
#pragma unroll
        for (int t = 0; t < 4; t++) {
            sred[w * 32 + t * 8 + lane * 2]     = part[2 * t];
            sred[w * 32 + t * 8 + lane * 2 + 1] = part[2 * t + 1];
        }
    }
    __syncthreads();
    if (tid < BB) {
        float tot = 0.0f;
#pragma unroll
        for (int ww = 0; ww < 8; ww++) tot += sred[ww * 32 + tid];
        out[tid * CC + c] = -tot;   // scores[b, c]
    }
}

extern "C" void kernel_launch(void* const* d_in, const int* in_sizes, int n_in,
                              void* d_out, int out_size) {
    (void)in_sizes; (void)n_in; (void)out_size;
    const float* x  = (const float*)d_in[0];   // raw_features [32,768]
    const float* mu = (const float*)d_in[1];   // class_means  [256,768]
    const float* g  = (const float*)d_in[2];   // class_diags  [256,768]
    const float* M  = (const float*)d_in[3];   // class_cov_invs [256,768,768]
    float* out = (float*)d_out;                // scores [32,256]

    const size_t smem_bytes = SMEM_FLOATS * sizeof(float);   // ~151.5 KB
    cudaFuncSetAttribute(fecam_score_kernel,
                         cudaFuncAttributeMaxDynamicSharedMemorySize,
                         (int)smem_bytes);
    fecam_score_kernel<<<CC, 256, smem_bytes>>>(x, mu, g, M, out);
}

// round 5
// speedup vs baseline: 1.8338x; 1.8338x over previous
#include <cuda_runtime.h>
#include <cstdint>

// Problem constants
#define BB 32
#define CC 256
#define DD 768

// Tiling
#define DTILE 128                  // d rows per d-tile (16 per warp x 8 warps)
#define KSTEP 32                   // e columns per pipeline stage
#define NDTILES (DD / DTILE)       // 6
#define KSTAGES (DD / KSTEP)       // 24
#define NTOT (NDTILES * KSTAGES)   // 144 stages
#define SBUF 6                     // per-warp ring depth
#define LOOKAHEAD 5                // stages issued ahead (SBUF-1)

#define WROWS 16                   // d rows per warp
#define LSTG 36                    // stage row stride (words); 36%32==4 -> conflict-free A LDS
#define WSTG (WROWS * LSTG)        // 576 words / stage / warp
#define LDIFF 772                  // diff row stride (words); 772%32==4 -> conflict-free B LDS.128

#define DIFF_SZ (BB * LDIFF)               // 24704 words
#define SMEM_WORDS (DIFF_SZ + 8 * SBUF * WSTG + 256)   // ~205.5 KB

// e-permutation within each 32-block: groups e%4 together so that the
// {q, q+4, q+8, ...} TF32 B-fragment elements become contiguous (LDS.128-able).
#define PERM(e) (((e) & ~31) | (((e) & 3) << 3) | (((e) >> 2) & 7))

__device__ __forceinline__ uint32_t f2tf(float f) {
    uint32_t r;
    asm("cvt.rna.tf32.f32 %0, %1;\n" : "=r"(r) : "f"(f));
    return r;
}

__device__ __forceinline__ void mma_tf32(float* c,
                                         uint32_t a0, uint32_t a1, uint32_t a2, uint32_t a3,
                                         uint32_t b0, uint32_t b1) {
    asm volatile(
        "mma.sync.aligned.m16n8k8.row.col.f32.tf32.tf32.f32 "
        "{%0,%1,%2,%3}, {%4,%5,%6,%7}, {%8,%9}, {%0,%1,%2,%3};\n"
        : "+f"(c[0]), "+f"(c[1]), "+f"(c[2]), "+f"(c[3])
        : "r"(a0), "r"(a1), "r"(a2), "r"(a3), "r"(b0), "r"(b1));
}

__device__ __forceinline__ void cp_async16(float* sdst, const float* gsrc) {
    unsigned saddr = (unsigned)__cvta_generic_to_shared(sdst);
    asm volatile("cp.async.cg.shared.global [%0], [%1], 16;\n"
                 :: "r"(saddr), "l"(gsrc));
}
__device__ __forceinline__ void cp_commit() {
    asm volatile("cp.async.commit_group;\n" ::: "memory");
}

// Warp-private stage load: 16 rows x 32 cols of M for this warp's d-slab.
// 128 x 16B chunks, 4 per lane; 8 lanes cover one full 128B gmem line.
__device__ __forceinline__ void issue_stage_w(const float* __restrict__ Mbase,
                                              float* __restrict__ wstg,
                                              int s, int w, int lane) {
    const int dt = s / KSTAGES;
    const int ks = s - dt * KSTAGES;
    const float* base = Mbase + (size_t)(dt * DTILE + w * WROWS) * DD + ks * KSTEP;
    float* dst = wstg + (s % SBUF) * WSTG;
#pragma unroll
    for (int j = 0; j < 4; j++) {
        int idx = lane + 32 * j;      // 0..127
        int r   = idx >> 3;           // 0..15
        int c4  = (idx & 7) << 2;     // 0,4,...,28
        cp_async16(dst + r * LSTG + c4, base + (size_t)r * DD + c4);
    }
    cp_commit();
}

__global__ void __launch_bounds__(256, 1)
fecam_score_kernel(const float* __restrict__ x,      // [32,768]
                   const float* __restrict__ mu,     // [256,768]
                   const float* __restrict__ g,      // [256,768]
                   const float* __restrict__ Minv,   // [256,768,768]
                   float* __restrict__ out)          // [32,256]
{
    extern __shared__ float smem[];
    float* sdiff = smem;                               // [32][772], e-permuted, tf32-rounded
    float* sstg  = smem + DIFF_SZ;                     // 8 x SBUF x [16][36]
    float* sred  = smem + DIFF_SZ + 8 * SBUF * WSTG;   // [8][32]

    const int c    = blockIdx.x;
    const int tid  = threadIdx.x;
    const int w    = tid >> 5;
    const int lane = tid & 31;
    const int grp  = lane >> 2;   // 0..7
    const int q    = lane & 3;    // 0..3

    const float* Mbase = Minv + (size_t)c * DD * DD;
    float* wstg = sstg + w * (SBUF * WSTG);

    // ---- Prologue: start streaming M before anything else ----
#pragma unroll
    for (int p = 0; p < LOOKAHEAD; p++)
        issue_stage_w(Mbase, wstg, p, w, lane);

    // ---- Phase 1: diff[b][e] = (x[b][e]-mu[c][e])/g[c][e], TF32-rounded,
    //      stored e-permuted in smem ----
    {
        float rcp[3], mun[3];
        int   pe[3];
#pragma unroll
        for (int i = 0; i < 3; i++) {
            int e = tid + i * 256;
            float gg = g[(size_t)c * DD + e];
            rcp[i] = 1.0f / gg;
            mun[i] = mu[(size_t)c * DD + e] * rcp[i];
            pe[i]  = PERM(e);
        }
        for (int b = 0; b < BB; b++) {
#pragma unroll
            for (int i = 0; i < 3; i++) {
                int e = tid + i * 256;
                float d = x[b * DD + e] * rcp[i] - mun[i];
                sdiff[b * LDIFF + pe[i]] = __uint_as_float(f2tf(d));
            }
        }
    }
    __syncthreads();

    // Accumulators: warp owns d rows [dt*128 + w*16, +16), all 32 batch cols.
    float acc[4][4];
#pragma unroll
    for (int t = 0; t < 4; t++)
#pragma unroll
        for (int i = 0; i < 4; i++) acc[t][i] = 0.0f;

    float part[8];
#pragma unroll
    for (int i = 0; i < 8; i++) part[i] = 0.0f;

    // ---- Mainloop: warp-private cp.async pipeline, no CTA barriers ----
    int dt = 0, ks = 0, buf = 0;
    for (int s = 0; s < NTOT; s++) {
        asm volatile("cp.async.wait_group 4;\n" ::: "memory");
        __syncwarp();

        if (s + LOOKAHEAD < NTOT) issue_stage_w(Mbase, wstg, s + LOOKAHEAD, w, lane);
        else                      cp_commit();   // keep group count invariant

        const float* stg = wstg + buf * WSTG;

        // B fragments for all 4 n-tiles, all 4 k-steps: 8x LDS.128 (conflict-free)
        uint4 bv[4][2];
        {
            const float* dB = sdiff + ks * KSTEP + (q << 3);
#pragma unroll
            for (int t = 0; t < 4; t++) {
                const uint4* p = (const uint4*)(dB + (t * 8 + grp) * LDIFF);
                bv[t][0] = p[0];
                bv[t][1] = p[1];
            }
        }

#pragma unroll
        for (int kk = 0; kk < 4; kk++) {
            const float* ap = stg + grp * LSTG + kk * 8 + q;
            uint32_t a0 = f2tf(ap[0]);
            uint32_t a1 = f2tf(ap[8 * LSTG]);
            uint32_t a2 = f2tf(ap[4]);
            uint32_t a3 = f2tf(ap[8 * LSTG + 4]);
#pragma unroll
            for (int t = 0; t < 4; t++) {
                uint32_t b0, b1;
                if      (kk == 0) { b0 = bv[t][0].x; b1 = bv[t][0].y; }
                else if (kk == 1) { b0 = bv[t][0].z; b1 = bv[t][0].w; }
                else if (kk == 2) { b0 = bv[t][1].x; b1 = bv[t][1].y; }
                else              { b0 = bv[t][1].z; b1 = bv[t][1].w; }
                mma_tf32(acc[t], a0, a1, a2, a3, b0, b1);
            }
        }

        // End of d-tile: fold u[b,d] into dist partials (diff index is permuted)
        if (ks == KSTAGES - 1) {
            const int dA  = dt * DTILE + (w << 4) + grp;
            const int pd0 = PERM(dA);
            const int pd1 = PERM(dA + 8);
#pragma unroll
            for (int t = 0; t < 4; t++) {
                const int b0i = t * 8 + (q << 1);
                part[2 * t]     += sdiff[b0i * LDIFF + pd0] * acc[t][0]
                                 + sdiff[b0i * LDIFF + pd1] * acc[t][2];
                part[2 * t + 1] += sdiff[(b0i + 1) * LDIFF + pd0] * acc[t][1]
                                 + sdiff[(b0i + 1) * LDIFF + pd1] * acc[t][3];
                acc[t][0] = acc[t][1] = acc[t][2] = acc[t][3] = 0.0f;
            }
            ks = 0; dt++;
        } else {
            ks++;
        }
        buf++; if (buf == SBUF) buf = 0;
    }

    // ---- Reduce: lanes sharing q hold the same b set; reduce over grp bits ----
#pragma unroll
    for (int i = 0; i < 8; i++) {
        part[i] += __shfl_xor_sync(0xffffffffu, part[i], 4);
        part[i] += __shfl_xor_sync(0xffffffffu, part[i], 8);
        part[i] += __shfl_xor_sync(0xffffffffu, part[i], 16);
    }
    if (lane < 4) {
#pragma unroll
        for (int t = 0; t < 4; t++) {
            sred[w * 32 + t * 8 + lane * 2]     = part[2 * t];
            sred[w * 32 + t * 8 + lane * 2 + 1] = part[2 * t + 1];
        }
    }
    __syncthreads();
    if (tid < BB) {
        float tot = 0.0f;
#pragma unroll
        for (int ww = 0; ww < 8; ww++) tot += sred[ww * 32 + tid];
        out[tid * CC + c] = -tot;   // scores[b, c]
    }
}

extern "C" void kernel_launch(void* const* d_in, const int* in_sizes, int n_in,
                              void* d_out, int out_size) {
    (void)in_sizes; (void)n_in; (void)out_size;
    const float* x  = (const float*)d_in[0];   // raw_features  [32,768]
    const float* mu = (const float*)d_in[1];   // class_means   [256,768]
    const float* g  = (const float*)d_in[2];   // class_diags   [256,768]
    const float* M  = (const float*)d_in[3];   // class_cov_invs [256,768,768]
    float* out = (float*)d_out;                // scores [32,256]

    const size_t smem_bytes = SMEM_WORDS * sizeof(float);   // ~205.5 KB
    cudaFuncSetAttribute(fecam_score_kernel,
                         cudaFuncAttributeMaxDynamicSharedMemorySize,
                         (int)smem_bytes);
    fecam_score_kernel<<<CC, 256, smem_bytes>>>(x, mu, g, M, out);
}

// round 6
// speedup vs baseline: 1.8556x; 1.0119x over previous
#include <cuda_runtime.h>
#include <cstdint>

// Problem constants
#define BB 32
#define CC 256
#define DD 768

// Tiling
#define DTILE 128                  // d rows per d-tile (16 per warp x 8 warps)
#define KSTEP 32                   // e columns per pipeline stage
#define NDTILES (DD / DTILE)       // 6
#define KSTAGES (DD / KSTEP)       // 24
#define NTOT (NDTILES * KSTAGES)   // 144 stages (order: s = ks*6 + dt)
#define SBUF 6                     // per-warp ring depth; buf == dt statically
#define LOOKAHEAD 5                // stages issued ahead

#define WROWS 16                   // d rows per warp
#define LSTG 36                    // stage row stride (words); 36%32==4 -> conflict-free A LDS
#define WSTG (WROWS * LSTG)        // 576 words / stage / warp
#define LDIFF 772                  // diff row stride (words); 772%32==4 -> conflict-free B LDS.128

#define DIFF_SZ (BB * LDIFF)                            // 24704 words
#define SMEM_WORDS (DIFF_SZ + 8 * SBUF * WSTG + 256)    // ~205.5 KB

// e-permutation within each 32-block: groups e%4 together so that the
// {q, q+4, q+8, ...} TF32 B-fragment elements become contiguous (LDS.128-able).
#define PERM(e) (((e) & ~31) | (((e) & 3) << 3) | (((e) >> 2) & 7))

__device__ __forceinline__ uint32_t f2tf(float f) {
    uint32_t r;
    asm("cvt.rna.tf32.f32 %0, %1;\n" : "=r"(r) : "f"(f));
    return r;
}

__device__ __forceinline__ void mma_tf32(float* c,
                                         uint32_t a0, uint32_t a1, uint32_t a2, uint32_t a3,
                                         uint32_t b0, uint32_t b1) {
    asm volatile(
        "mma.sync.aligned.m16n8k8.row.col.f32.tf32.tf32.f32 "
        "{%0,%1,%2,%3}, {%4,%5,%6,%7}, {%8,%9}, {%0,%1,%2,%3};\n"
        : "+f"(c[0]), "+f"(c[1]), "+f"(c[2]), "+f"(c[3])
        : "r"(a0), "r"(a1), "r"(a2), "r"(a3), "r"(b0), "r"(b1));
}

__device__ __forceinline__ void cp_async16(float* sdst, const float* gsrc) {
    unsigned saddr = (unsigned)__cvta_generic_to_shared(sdst);
    asm volatile("cp.async.cg.shared.global [%0], [%1], 16;\n"
                 :: "r"(saddr), "l"(gsrc));
}
__device__ __forceinline__ void cp_commit() {
    asm volatile("cp.async.commit_group;\n" ::: "memory");
}

// Warp-private stage load: 16 rows x 32 cols of M for this warp's d-slab.
// Stage s = ks*6 + dt. 128 x 16B chunks, 4 per lane.
__device__ __forceinline__ void issue_stage_w(const float* __restrict__ Mbase,
                                              float* __restrict__ wstg,
                                              int s, int w, int lane) {
    const int dt = s % NDTILES;
    const int ks = s / NDTILES;
    const float* base = Mbase + (size_t)(dt * DTILE + w * WROWS) * DD + ks * KSTEP;
    float* dst = wstg + (s % SBUF) * WSTG;
#pragma unroll
    for (int j = 0; j < 4; j++) {
        int idx = lane + 32 * j;      // 0..127
        int r   = idx >> 3;           // 0..15
        int c4  = (idx & 7) << 2;     // 0,4,...,28
        cp_async16(dst + r * LSTG + c4, base + (size_t)r * DD + c4);
    }
    cp_commit();
}

__global__ void __launch_bounds__(256, 1)
fecam_score_kernel(const float* __restrict__ x,      // [32,768]
                   const float* __restrict__ mu,     // [256,768]
                   const float* __restrict__ g,      // [256,768]
                   const float* __restrict__ Minv,   // [256,768,768]
                   float* __restrict__ out)          // [32,256]
{
    extern __shared__ float smem[];
    float* sdiff = smem;                               // [32][772], e-permuted, tf32-rounded
    float* sstg  = smem + DIFF_SZ;                     // 8 x SBUF x [16][36]
    float* sred  = smem + DIFF_SZ + 8 * SBUF * WSTG;   // [8][32]

    const int c    = blockIdx.x;
    const int tid  = threadIdx.x;
    const int w    = tid >> 5;
    const int lane = tid & 31;
    const int grp  = lane >> 2;   // 0..7
    const int q    = lane & 3;    // 0..3

    const float* Mbase = Minv + (size_t)c * DD * DD;
    float* wstg = sstg + w * (SBUF * WSTG);

    // ---- Prologue: start streaming M before anything else ----
#pragma unroll
    for (int p = 0; p < LOOKAHEAD; p++)
        issue_stage_w(Mbase, wstg, p, w, lane);

    // ---- Phase 1: diff[b][e] = (x[b][e]-mu[c][e])/g[c][e], TF32-rounded,
    //      stored e-permuted in smem ----
    {
        float rcp[3], mun[3];
        int   pe[3];
#pragma unroll
        for (int i = 0; i < 3; i++) {
            int e = tid + i * 256;
            float gg = g[(size_t)c * DD + e];
            rcp[i] = 1.0f / gg;
            mun[i] = mu[(size_t)c * DD + e] * rcp[i];
            pe[i]  = PERM(e);
        }
        for (int b = 0; b < BB; b++) {
#pragma unroll
            for (int i = 0; i < 3; i++) {
                int e = tid + i * 256;
                float d = x[b * DD + e] * rcp[i] - mun[i];
                sdiff[b * LDIFF + pe[i]] = __uint_as_float(f2tf(d));
            }
        }
    }
    __syncthreads();

    // Accumulators for ALL six d-tiles (ks-outer loop): warp owns rows
    // [dt*128 + w*16, +16) for every dt; acc[dt][t] = C frag for n-tile t.
    float acc[NDTILES][4][4];
#pragma unroll
    for (int dt = 0; dt < NDTILES; dt++)
#pragma unroll
        for (int t = 0; t < 4; t++)
#pragma unroll
            for (int i = 0; i < 4; i++) acc[dt][t][i] = 0.0f;

    // ---- Mainloop: ks outer (B fragments loaded ONCE per ks), dt inner ----
    for (int ks = 0; ks < KSTAGES; ks++) {
        // B fragments for all 4 n-tiles, all 4 k-steps: 8x LDS.128 (conflict-free),
        // reused across the 6 d-tiles below.
        uint4 bv[4][2];
        {
            const float* dB = sdiff + ks * KSTEP + (q << 3);
#pragma unroll
            for (int t = 0; t < 4; t++) {
                const uint4* p = (const uint4*)(dB + (t * 8 + grp) * LDIFF);
                bv[t][0] = p[0];
                bv[t][1] = p[1];
            }
        }

#pragma unroll
        for (int dt = 0; dt < NDTILES; dt++) {
            const int s = ks * NDTILES + dt;     // current stage; buf = s%6 = dt
            asm volatile("cp.async.wait_group 4;\n" ::: "memory");
            __syncwarp();

            if (s + LOOKAHEAD < NTOT) issue_stage_w(Mbase, wstg, s + LOOKAHEAD, w, lane);
            else                      cp_commit();   // keep group-count invariant

            const float* stg = wstg + dt * WSTG;     // static buffer index

#pragma unroll
            for (int kk = 0; kk < 4; kk++) {
                const float* ap = stg + grp * LSTG + kk * 8 + q;
                uint32_t a0 = f2tf(ap[0]);
                uint32_t a1 = f2tf(ap[8 * LSTG]);
                uint32_t a2 = f2tf(ap[4]);
                uint32_t a3 = f2tf(ap[8 * LSTG + 4]);
#pragma unroll
                for (int t = 0; t < 4; t++) {
                    uint32_t b0, b1;
                    if      (kk == 0) { b0 = bv[t][0].x; b1 = bv[t][0].y; }
                    else if (kk == 1) { b0 = bv[t][0].z; b1 = bv[t][0].w; }
                    else if (kk == 2) { b0 = bv[t][1].x; b1 = bv[t][1].y; }
                    else              { b0 = bv[t][1].z; b1 = bv[t][1].w; }
                    mma_tf32(acc[dt][t], a0, a1, a2, a3, b0, b1);
                }
            }
        }
    }

    // ---- Epilogue: fold u[b,d] into dist partials with fp32 diff ----
    float part[8];
#pragma unroll
    for (int i = 0; i < 8; i++) part[i] = 0.0f;

#pragma unroll
    for (int dt = 0; dt < NDTILES; dt++) {
        const int dA  = dt * DTILE + (w << 4) + grp;
        const int pd0 = PERM(dA);
        const int pd1 = PERM(dA + 8);
#pragma unroll
        for (int t = 0; t < 4; t++) {
            const int b0i = t * 8 + (q << 1);
            part[2 * t]     += sdiff[b0i * LDIFF + pd0] * acc[dt][t][0]
                             + sdiff[b0i * LDIFF + pd1] * acc[dt][t][2];
            part[2 * t + 1] += sdiff[(b0i + 1) * LDIFF + pd0] * acc[dt][t][1]
                             + sdiff[(b0i + 1) * LDIFF + pd1] * acc[dt][t][3];
        }
    }

    // ---- Reduce: lanes sharing q hold the same b set; reduce over grp bits ----
#pragma unroll
    for (int i = 0; i < 8; i++) {
        part[i] += __shfl_xor_sync(0xffffffffu, part[i], 4);
        part[i] += __shfl_xor_sync(0xffffffffu, part[i], 8);
        part[i] += __shfl_xor_sync(0xffffffffu, part[i], 16);
    }
    if (lane < 4) {
#pragma unroll
        for (int t = 0; t < 4; t++) {
            sred[w * 32 + t * 8 + lane * 2]     = part[2 * t];
            sred[w * 32 + t * 8 + lane * 2 + 1] = part[2 * t + 1];
        }
    }
    __syncthreads();
    if (tid < BB) {
        float tot = 0.0f;
#pragma unroll
        for (int ww = 0; ww < 8; ww++) tot += sred[ww * 32 + tid];
        out[tid * CC + c] = -tot;   // scores[b, c]
    }
}

extern "C" void kernel_launch(void* const* d_in, const int* in_sizes, int n_in,
                              void* d_out, int out_size) {
    (void)in_sizes; (void)n_in; (void)out_size;
    const float* x  = (const float*)d_in[0];   // raw_features   [32,768]
    const float* mu = (const float*)d_in[1];   // class_means    [256,768]
    const float* g  = (const float*)d_in[2];   // class_diags    [256,768]
    const float* M  = (const float*)d_in[3];   // class_cov_invs [256,768,768]
    float* out = (float*)d_out;                // scores [32,256]

    const size_t smem_bytes = SMEM_WORDS * sizeof(float);   // ~205.5 KB
    cudaFuncSetAttribute(fecam_score_kernel,
                         cudaFuncAttributeMaxDynamicSharedMemorySize,
                         (int)smem_bytes);
    fecam_score_kernel<<<CC, 256, smem_bytes>>>(x, mu, g, M, out);
}